// round 15
// baseline (speedup 1.0000x reference)
#include <cuda_runtime.h>
#include <cuda_bf16.h>
#include <cstdint>

// ---------------------------------------------------------------------------
// TemporalGCN: conv1+relu+pool -> conv2+relu+pool -> GCN1 -> GCN2 -> mean -> fc
// B=1024, C_IN=9, T=2048, RT=512, HID=128, OUT=64
//
// R9 (resubmit; GPU timeouts): split bf16 weights precomputed ONCE by prep
// kernels (per-block pksplit ALU removed from the GCN GEMMs); convs
// restructured for occupancy (conv1: 256 thr / 256 pos, accumulator-array
// form; conv2: 256 thr, co-split). GCN GEMMs: bf16 mma.m16n8k16, W split
// hi+lo (2 accumulating passes), chain-stencil folded into A, GCN2 epilogue
// = relu + per-batch column sums.
// ---------------------------------------------------------------------------

#define B_      1024
#define T_      2048
#define T1_     1024
#define RT_     512
#define HID_    128

static __device__ float          g_o1[(size_t)B_ * 16 * T1_];   // conv1 out
static __device__ float          g_o2[(size_t)B_ * 32 * RT_];   // conv2 out
static __device__ __nv_bfloat16  g_h1[(size_t)B_ * RT_ * HID_]; // gcn1 out (bf16)
static __device__ float          g_bsum[(size_t)B_ * 4 * HID_]; // per-(b,chunk) colsums
static __device__ uint2          g_w1s[2][8][128];              // [hi/lo][f][n] split W1
static __device__ uint2          g_w2s[2][4][8][128];           // [hi/lo][ch][f][n] split W2

__device__ __forceinline__ unsigned long long dup2(float a) {
    unsigned ai = __float_as_uint(a);
    unsigned long long r;
    asm("mov.b64 %0, {%1, %1};" : "=l"(r) : "r"(ai));
    return r;
}
__device__ __forceinline__ unsigned long long packf2(float lo, float hi) {
    unsigned long long r;
    asm("mov.b64 %0, {%1, %2};" : "=l"(r) : "f"(lo), "f"(hi));
    return r;
}
#define FFMA2(d, a, b) asm("fma.rn.f32x2 %0, %1, %2, %0;" : "+l"(d) : "l"(a), "l"(b))

__device__ __forceinline__ unsigned pk(float lo, float hi) {
    __nv_bfloat162 t = __floats2bfloat162_rn(lo, hi);
    return *(unsigned*)&t;
}
__device__ __forceinline__ float2 upk(unsigned u) {
    return __bfloat1622float2(*(__nv_bfloat162*)&u);
}
__device__ __forceinline__ void pksplit(float a, float b, unsigned& hi, unsigned& lo) {
    __nv_bfloat16 ah = __float2bfloat16(a);
    __nv_bfloat16 bh = __float2bfloat16(b);
    __nv_bfloat162 h2;
    h2.x = ah; h2.y = bh;
    hi = *(unsigned*)&h2;
    lo = pk(a - __bfloat162float(ah), b - __bfloat162float(bh));
}

__device__ __forceinline__ void mma_bf16(float c[4],
                                         unsigned a0, unsigned a1, unsigned a2, unsigned a3,
                                         unsigned b0, unsigned b1) {
    asm volatile(
        "mma.sync.aligned.m16n8k16.row.col.f32.bf16.bf16.f32 "
        "{%0,%1,%2,%3},{%4,%5,%6,%7},{%8,%9},{%0,%1,%2,%3};"
        : "+f"(c[0]), "+f"(c[1]), "+f"(c[2]), "+f"(c[3])
        : "r"(a0), "r"(a1), "r"(a2), "r"(a3), "r"(b0), "r"(b1));
}

#define RS2 0.70710678118654752f   // 2^-1/2
#define RS3 0.57735026918962576f   // 3^-1/2

// ---------------------------------------------------------------------------
// prep kernels: split W1/W2 into hi/lo bf16x2 words in final mma layout
// ---------------------------------------------------------------------------
__global__ void prep_w1_kernel(const float* __restrict__ W) {
    int t = blockIdx.x * 256 + threadIdx.x;
    if (t >= 8 * 128) return;
    int f = t >> 7, n = t & 127;
    int ks = f >> 2, klo = f & 3;
    int ka = 2 * (ks * 8 + klo);
    unsigned hx, lx, hy, ly;
    pksplit(W[ka * HID_ + n], W[(ka + 1) * HID_ + n], hx, lx);
    pksplit(W[(ka + 8) * HID_ + n], W[(ka + 9) * HID_ + n], hy, ly);
    uint2 vh; vh.x = hx; vh.y = hy;
    uint2 vl; vl.x = lx; vl.y = ly;
    g_w1s[0][f][n] = vh;
    g_w1s[1][f][n] = vl;
}

__global__ void prep_w2_kernel(const float* __restrict__ W) {
    int t = blockIdx.x * 256 + threadIdx.x;
    if (t >= 4 * 8 * 128) return;
    int ch = t >> 10, f = (t >> 7) & 7, n = t & 127;
    int ks = f >> 2, klo = f & 3;
    int ka = ch * 32 + 2 * (ks * 8 + klo);
    unsigned hx, lx, hy, ly;
    pksplit(W[ka * HID_ + n], W[(ka + 1) * HID_ + n], hx, lx);
    pksplit(W[(ka + 8) * HID_ + n], W[(ka + 9) * HID_ + n], hy, ly);
    uint2 vh; vh.x = hx; vh.y = hy;
    uint2 vl; vl.x = lx; vl.y = ly;
    g_w2s[0][ch][f][n] = vh;
    g_w2s[1][ch][f][n] = vl;
}

// ---------------------------------------------------------------------------
// conv1 + relu + maxpool2 : x[B,9,2048] -> g_o1[B,16,1024]
// grid (1024, 4), 256 threads; 256 pooled positions per block
// ---------------------------------------------------------------------------
__global__ __launch_bounds__(256) void conv1_kernel(const float* __restrict__ x,
                                                    const float* __restrict__ w,
                                                    const float* __restrict__ bias) {
    __shared__ float xs[9][516];
    __shared__ unsigned long long ws2[720];
    __shared__ float bs[16];
    const int b = blockIdx.x, t0 = blockIdx.y * 256, tid = threadIdx.x;

    for (int e = tid; e < 720; e += 256) ws2[e] = dup2(w[e]);
    if (tid < 16) bs[tid] = bias[tid];

    const float* xb = x + (size_t)b * 9 * T_;
    const int base = 2 * t0 - 2;
    for (int e = tid; e < 9 * 516; e += 256) {
        int ci = e / 516, j = e % 516;
        int t = base + j;
        xs[ci][j] = (t >= 0 && t < T_) ? xb[ci * T_ + t] : 0.f;
    }
    __syncthreads();

    const int lt = tid;
    unsigned long long a[16];
#pragma unroll
    for (int co = 0; co < 16; co++) a[co] = 0ull;

#pragma unroll
    for (int ci = 0; ci < 9; ci++) {
        float xv[6];
#pragma unroll
        for (int j = 0; j < 6; j++) xv[j] = xs[ci][2 * lt + j];
        unsigned long long xp[5];
#pragma unroll
        for (int k = 0; k < 5; k++) xp[k] = packf2(xv[k], xv[k + 1]);
#pragma unroll
        for (int co = 0; co < 16; co++)
#pragma unroll
            for (int k = 0; k < 5; k++)
                FFMA2(a[co], ws2[(co * 9 + ci) * 5 + k], xp[k]);
    }

    float* ob = g_o1 + (size_t)b * 16 * T1_ + (t0 + lt);
#pragma unroll
    for (int co = 0; co < 16; co++) {
        float lo = __uint_as_float((unsigned)(a[co] & 0xffffffffull));
        float hi = __uint_as_float((unsigned)(a[co] >> 32));
        ob[(size_t)co * T1_] = fmaxf(fmaxf(lo, hi) + bs[co], 0.f);
    }
}

// ---------------------------------------------------------------------------
// conv2 + relu + maxpool2 : g_o1[B,16,1024] -> g_o2[B,32,512]
// grid (1024, 4), 256 threads; 128 positions x 2 co-halves (16 co each)
// ---------------------------------------------------------------------------
__global__ __launch_bounds__(256) void conv2_kernel(const float* __restrict__ w,
                                                    const float* __restrict__ bias) {
    __shared__ float xs[16][260];
    __shared__ unsigned long long ws2[2560];
    __shared__ float bs[32];
    const int b = blockIdx.x, t0 = blockIdx.y * 128, tid = threadIdx.x;

    for (int e = tid; e < 2560; e += 256) ws2[e] = dup2(w[e]);
    if (tid < 32) bs[tid] = bias[tid];

    const float* xb = g_o1 + (size_t)b * 16 * T1_;
    const int base = 2 * t0 - 2;
    for (int e = tid; e < 16 * 260; e += 256) {
        int ci = e / 260, j = e % 260;
        int t = base + j;
        xs[ci][j] = (t >= 0 && t < T1_) ? xb[ci * T1_ + t] : 0.f;
    }
    __syncthreads();

    const int lt = tid & 127;          // pooled position within tile
    const int cob = (tid >> 7) * 16;   // co 0-15 or 16-31
    unsigned long long a[16];
#pragma unroll
    for (int co = 0; co < 16; co++) a[co] = 0ull;

#pragma unroll
    for (int ci = 0; ci < 16; ci++) {
        float xv[6];
#pragma unroll
        for (int j = 0; j < 6; j++) xv[j] = xs[ci][2 * lt + j];
        unsigned long long xp[5];
#pragma unroll
        for (int k = 0; k < 5; k++) xp[k] = packf2(xv[k], xv[k + 1]);
#pragma unroll
        for (int co = 0; co < 16; co++)
#pragma unroll
            for (int k = 0; k < 5; k++)
                FFMA2(a[co], ws2[((cob + co) * 16 + ci) * 5 + k], xp[k]);
    }

    float* ob = g_o2 + (size_t)b * 32 * RT_ + (t0 + lt);
#pragma unroll
    for (int co = 0; co < 16; co++) {
        float lo = __uint_as_float((unsigned)(a[co] & 0xffffffffull));
        float hi = __uint_as_float((unsigned)(a[co] >> 32));
        ob[(size_t)(cob + co) * RT_] = fmaxf(fmaxf(lo, hi) + bs[cob + co], 0.f);
    }
}

// ---------------------------------------------------------------------------
// GCN1 (bf16 mma, pre-split W): z = Anorm*o2 (stencil), h1 = relu(z@W1+b1)
// 128 rows x 128 cols, K=32 (2 ksteps). 8 warps = 4m x 2n. grid 4096.
// ---------------------------------------------------------------------------
__global__ __launch_bounds__(256) void gcn1_kernel(const float* __restrict__ bias) {
    __shared__ uint2 za[16][68];
    __shared__ uint2 wph[8][132];
    __shared__ uint2 wpl[8][132];
    __shared__ float bsm[128];
    const int bx = blockIdx.x, b = bx >> 2, p0 = (bx & 3) << 7;
    const int tid = threadIdx.x, lane = tid & 31, warp = tid >> 5;
    const int wm = warp >> 1, wn = warp & 1, l4 = lane & 3, l8 = lane >> 2;

    if (tid < 128) bsm[tid] = bias[tid];

    // fill wph/wpl from pre-split weights (coalesced uint2 copies)
    for (int e = tid; e < 1024; e += 256) {
        int f = e >> 7, n = e & 127;
        wph[f][n] = g_w1s[0][f][n];
        wpl[f][n] = g_w1s[1][f][n];
    }
    // fill za: stencil over g_o2 [b][32 f][512 p]
    {
        const float* gb = g_o2 + (size_t)b * 32 * RT_;
        const int kp = 2 * warp + (lane >> 4);
        const int rl = lane & 15;
#pragma unroll
        for (int i = 0; i < 4; i++) {
            int ridx = rl + 16 * i;
            int r0 = ((ridx >> 3) << 4) + (ridx & 7);
            uint2 v;
#pragma unroll
            for (int h = 0; h < 2; h++) {
                int pp = p0 + r0 + h * 8;
                float di = (pp == 0 || pp == RT_ - 1) ? RS2 : RS3;
                const float* c0 = gb + (2 * kp) * RT_ + pp;
                const float* c1 = gb + (2 * kp + 1) * RT_ + pp;
                float z0 = di * di * c0[0];
                float z1 = di * di * c1[0];
                if (pp > 0) {
                    float dp = (pp == 1) ? RS2 : RS3;
                    z0 += di * dp * c0[-1];
                    z1 += di * dp * c1[-1];
                }
                if (pp < RT_ - 1) {
                    float dn = (pp == RT_ - 2) ? RS2 : RS3;
                    z0 += di * dn * c0[1];
                    z1 += di * dn * c1[1];
                }
                unsigned wv = pk(z0, z1);
                if (h == 0) v.x = wv; else v.y = wv;
            }
            za[kp][ridx] = v;
        }
    }
    __syncthreads();

    float acc[2][8][4] = {};
#pragma unroll
    for (int ks = 0; ks < 2; ks++) {
        unsigned a[2][4];
#pragma unroll
        for (int i = 0; i < 2; i++) {
            int mt = wm * 2 + i;
            uint2 lo = za[ks * 8 + l4][mt * 8 + l8];
            uint2 hi = za[ks * 8 + 4 + l4][mt * 8 + l8];
            a[i][0] = lo.x; a[i][1] = lo.y; a[i][2] = hi.x; a[i][3] = hi.y;
        }
#pragma unroll
        for (int j = 0; j < 8; j++) {
            uint2 bh = wph[ks * 4 + l4][wn * 64 + j * 8 + l8];
            uint2 bl = wpl[ks * 4 + l4][wn * 64 + j * 8 + l8];
#pragma unroll
            for (int i = 0; i < 2; i++) {
                mma_bf16(acc[i][j], a[i][0], a[i][1], a[i][2], a[i][3], bh.x, bh.y);
                mma_bf16(acc[i][j], a[i][0], a[i][1], a[i][2], a[i][3], bl.x, bl.y);
            }
        }
    }

    // epilogue: relu(acc + bias) -> g_h1 bf16x2 words
    unsigned* h1w = (unsigned*)g_h1;
#pragma unroll
    for (int i = 0; i < 2; i++) {
#pragma unroll
        for (int j = 0; j < 8; j++) {
            int cb = wn * 64 + j * 8 + 2 * l4;
            float b0 = bsm[cb], b1 = bsm[cb + 1];
            int R0 = wm * 32 + i * 16 + l8;
            size_t node = (size_t)b * RT_ + p0 + R0;
            int cw = cb >> 1;
            h1w[node * 64 + cw] =
                pk(fmaxf(acc[i][j][0] + b0, 0.f), fmaxf(acc[i][j][1] + b1, 0.f));
            h1w[(node + 8) * 64 + cw] =
                pk(fmaxf(acc[i][j][2] + b0, 0.f), fmaxf(acc[i][j][3] + b1, 0.f));
        }
    }
}

// ---------------------------------------------------------------------------
// GCN2 (bf16 mma, pre-split W): z2 = Anorm*h1 (stencil), acc = z2@W2,
// epilogue relu + bias + per-batch column sums -> g_bsum.
// 128 rows x 128 cols, K=128 in 4 chunks of 32 (2 ksteps each). grid 4096.
// ---------------------------------------------------------------------------
__global__ __launch_bounds__(256) void gcn2_kernel(const float* __restrict__ bias) {
    __shared__ uint2 za[16][68];
    __shared__ uint2 wph[8][132];
    __shared__ uint2 wpl[8][132];
    __shared__ float red[4][128];
    __shared__ float bsm[128];
    const int bx = blockIdx.x, b = bx >> 2, p0 = (bx & 3) << 7;
    const int tid = threadIdx.x, lane = tid & 31, warp = tid >> 5;
    const int wm = warp >> 1, wn = warp & 1, l4 = lane & 3, l8 = lane >> 2;

    if (tid < 128) bsm[tid] = bias[tid];

    float acc[2][8][4] = {};

    const unsigned* h1w = (const unsigned*)g_h1;
    const int fkp = tid & 15;          // k-pair 0..15 within chunk
    const int rb  = tid >> 4;          // ridx base 0..15

    for (int ch = 0; ch < 4; ch++) {
        const int k0 = ch * 32;
        if (ch) __syncthreads();
        // fill wph/wpl from pre-split weights
        for (int e = tid; e < 1024; e += 256) {
            int f = e >> 7, n = e & 127;
            wph[f][n] = g_w2s[0][ch][f][n];
            wpl[f][n] = g_w2s[1][ch][f][n];
        }
        // fill za: stencil over bf16 h1 words
        {
            const int cw = (k0 >> 1) + fkp;
#pragma unroll
            for (int i = 0; i < 4; i++) {
                int ridx = rb + 16 * i;
                int r0 = ((ridx >> 3) << 4) + (ridx & 7);
                uint2 v;
#pragma unroll
                for (int h = 0; h < 2; h++) {
                    int pp = p0 + r0 + h * 8;
                    size_t node = (size_t)b * RT_ + pp;
                    float di = (pp == 0 || pp == RT_ - 1) ? RS2 : RS3;
                    float2 c = upk(h1w[node * 64 + cw]);
                    float zx = di * di * c.x, zy = di * di * c.y;
                    if (pp > 0) {
                        float dp = (pp == 1) ? RS2 : RS3;
                        float2 t = upk(h1w[(node - 1) * 64 + cw]);
                        zx += di * dp * t.x; zy += di * dp * t.y;
                    }
                    if (pp < RT_ - 1) {
                        float dn = (pp == RT_ - 2) ? RS2 : RS3;
                        float2 t = upk(h1w[(node + 1) * 64 + cw]);
                        zx += di * dn * t.x; zy += di * dn * t.y;
                    }
                    unsigned wv = pk(zx, zy);
                    if (h == 0) v.x = wv; else v.y = wv;
                }
                za[fkp][ridx] = v;
            }
        }
        __syncthreads();

#pragma unroll
        for (int ks = 0; ks < 2; ks++) {
            unsigned a[2][4];
#pragma unroll
            for (int i = 0; i < 2; i++) {
                int mt = wm * 2 + i;
                uint2 lo = za[ks * 8 + l4][mt * 8 + l8];
                uint2 hi = za[ks * 8 + 4 + l4][mt * 8 + l8];
                a[i][0] = lo.x; a[i][1] = lo.y; a[i][2] = hi.x; a[i][3] = hi.y;
            }
#pragma unroll
            for (int j = 0; j < 8; j++) {
                uint2 bh = wph[ks * 4 + l4][wn * 64 + j * 8 + l8];
                uint2 bl = wpl[ks * 4 + l4][wn * 64 + j * 8 + l8];
#pragma unroll
                for (int i = 0; i < 2; i++) {
                    mma_bf16(acc[i][j], a[i][0], a[i][1], a[i][2], a[i][3], bh.x, bh.y);
                    mma_bf16(acc[i][j], a[i][0], a[i][1], a[i][2], a[i][3], bl.x, bl.y);
                }
            }
        }
    }

    // --- epilogue: relu(acc + bias), column sums, warp bfly reduce ---
    float s[8][2];
#pragma unroll
    for (int j = 0; j < 8; j++) {
        int colb = wn * 64 + j * 8 + 2 * l4;
        float b0v = bsm[colb], b1v = bsm[colb + 1];
        float s0 = 0.f, s1 = 0.f;
#pragma unroll
        for (int i = 0; i < 2; i++) {
            s0 += fmaxf(acc[i][j][0] + b0v, 0.f) + fmaxf(acc[i][j][2] + b0v, 0.f);
            s1 += fmaxf(acc[i][j][1] + b1v, 0.f) + fmaxf(acc[i][j][3] + b1v, 0.f);
        }
        s[j][0] = s0;
        s[j][1] = s1;
    }
#pragma unroll
    for (int j = 0; j < 8; j++)
#pragma unroll
        for (int lo = 0; lo < 2; lo++) {
            float v = s[j][lo];
            v += __shfl_xor_sync(0xffffffffu, v, 4);
            v += __shfl_xor_sync(0xffffffffu, v, 8);
            v += __shfl_xor_sync(0xffffffffu, v, 16);
            s[j][lo] = v;
        }
    if (lane < 4) {
#pragma unroll
        for (int j = 0; j < 8; j++)
#pragma unroll
            for (int lo = 0; lo < 2; lo++)
                red[wm][wn * 64 + j * 8 + 2 * lane + lo] = s[j][lo];
    }
    __syncthreads();

    if (tid < 128) {
        float t = red[0][tid] + red[1][tid] + red[2][tid] + red[3][tid];
        g_bsum[((size_t)b * 4 + (bx & 3)) * HID_ + tid] = t;
    }
}

// ---------------------------------------------------------------------------
// mean over RT (sum of 4 chunk partials / 512) then fc
// ---------------------------------------------------------------------------
__global__ void fc_kernel(const float* __restrict__ fw,
                          const float* __restrict__ fb,
                          float* __restrict__ out) {
    __shared__ float s[128];
    const int b = blockIdx.x, o = threadIdx.x;
    {
        float v0 = 0.f, v1 = 0.f;
#pragma unroll
        for (int c = 0; c < 4; c++) {
            v0 += g_bsum[((size_t)b * 4 + c) * HID_ + o];
            v1 += g_bsum[((size_t)b * 4 + c) * HID_ + o + 64];
        }
        s[o] = v0;
        s[o + 64] = v1;
    }
    __syncthreads();
    float a = 0.f;
#pragma unroll
    for (int k = 0; k < 128; k++) a += s[k] * fw[k * 64 + o];
    out[b * 64 + o] = a * (1.f / 512.f) + fb[o];
}

// ---------------------------------------------------------------------------
extern "C" void kernel_launch(void* const* d_in, const int* in_sizes, int n_in,
                              void* d_out, int out_size) {
    const float* x   = (const float*)d_in[0];
    const float* c1w = (const float*)d_in[1];
    const float* c1b = (const float*)d_in[2];
    const float* c2w = (const float*)d_in[3];
    const float* c2b = (const float*)d_in[4];
    const float* g1w = (const float*)d_in[5];
    const float* g1b = (const float*)d_in[6];
    const float* g2w = (const float*)d_in[7];
    const float* g2b = (const float*)d_in[8];
    const float* fw  = (const float*)d_in[9];
    const float* fb  = (const float*)d_in[10];
    float* out = (float*)d_out;

    prep_w1_kernel<<<4, 256>>>(g1w);
    prep_w2_kernel<<<16, 256>>>(g2w);
    conv1_kernel<<<dim3(B_, 4), 256>>>(x, c1w, c1b);
    conv2_kernel<<<dim3(B_, 4), 256>>>(c2w, c2b);
    gcn1_kernel<<<B_ * 4, 256>>>(g1b);
    gcn2_kernel<<<B_ * 4, 256>>>(g2b);
    fc_kernel<<<B_, 64>>>(fw, fb, out);
}

// round 16
// speedup vs baseline: 1.1151x; 1.1151x over previous
#include <cuda_runtime.h>
#include <cuda_bf16.h>
#include <cstdint>

// ---------------------------------------------------------------------------
// TemporalGCN: conv1+relu+pool -> conv2+relu+pool -> GCN1 -> GCN2 -> mean -> fc
// B=1024, C_IN=9, T=2048, RT=512, HID=128, OUT=64
//
// R16: convs reverted to the R8-measured forms (128-thread, f32x2-packed);
// GCN GEMMs keep R9's prep-kernel pre-split bf16 weights (validated inert,
// removes per-block pksplit ALU). bf16 mma.m16n8k16, W split hi+lo,
// chain-stencil folded into A, GCN2 epilogue = relu + per-batch column sums.
// ---------------------------------------------------------------------------

#define B_      1024
#define T_      2048
#define T1_     1024
#define RT_     512
#define HID_    128

static __device__ float          g_o1[(size_t)B_ * 16 * T1_];   // conv1 out
static __device__ float          g_o2[(size_t)B_ * 32 * RT_];   // conv2 out
static __device__ __nv_bfloat16  g_h1[(size_t)B_ * RT_ * HID_]; // gcn1 out (bf16)
static __device__ float          g_bsum[(size_t)B_ * 4 * HID_]; // per-(b,chunk) colsums
static __device__ uint2          g_w1s[2][8][128];              // [hi/lo][f][n] split W1
static __device__ uint2          g_w2s[2][4][8][128];           // [hi/lo][ch][f][n] split W2

__device__ __forceinline__ unsigned long long dup2(float a) {
    unsigned ai = __float_as_uint(a);
    unsigned long long r;
    asm("mov.b64 %0, {%1, %1};" : "=l"(r) : "r"(ai));
    return r;
}
__device__ __forceinline__ unsigned long long packf2(float lo, float hi) {
    unsigned long long r;
    asm("mov.b64 %0, {%1, %2};" : "=l"(r) : "f"(lo), "f"(hi));
    return r;
}
#define FFMA2(d, a, b) asm("fma.rn.f32x2 %0, %1, %2, %0;" : "+l"(d) : "l"(a), "l"(b))

__device__ __forceinline__ unsigned pk(float lo, float hi) {
    __nv_bfloat162 t = __floats2bfloat162_rn(lo, hi);
    return *(unsigned*)&t;
}
__device__ __forceinline__ float2 upk(unsigned u) {
    return __bfloat1622float2(*(__nv_bfloat162*)&u);
}
__device__ __forceinline__ void pksplit(float a, float b, unsigned& hi, unsigned& lo) {
    __nv_bfloat16 ah = __float2bfloat16(a);
    __nv_bfloat16 bh = __float2bfloat16(b);
    __nv_bfloat162 h2;
    h2.x = ah; h2.y = bh;
    hi = *(unsigned*)&h2;
    lo = pk(a - __bfloat162float(ah), b - __bfloat162float(bh));
}

__device__ __forceinline__ void mma_bf16(float c[4],
                                         unsigned a0, unsigned a1, unsigned a2, unsigned a3,
                                         unsigned b0, unsigned b1) {
    asm volatile(
        "mma.sync.aligned.m16n8k16.row.col.f32.bf16.bf16.f32 "
        "{%0,%1,%2,%3},{%4,%5,%6,%7},{%8,%9},{%0,%1,%2,%3};"
        : "+f"(c[0]), "+f"(c[1]), "+f"(c[2]), "+f"(c[3])
        : "r"(a0), "r"(a1), "r"(a2), "r"(a3), "r"(b0), "r"(b1));
}

#define RS2 0.70710678118654752f   // 2^-1/2
#define RS3 0.57735026918962576f   // 3^-1/2

// ---------------------------------------------------------------------------
// prep kernels: split W1/W2 into hi/lo bf16x2 words in final mma layout
// ---------------------------------------------------------------------------
__global__ void prep_w1_kernel(const float* __restrict__ W) {
    int t = blockIdx.x * 256 + threadIdx.x;
    if (t >= 8 * 128) return;
    int f = t >> 7, n = t & 127;
    int ks = f >> 2, klo = f & 3;
    int ka = 2 * (ks * 8 + klo);
    unsigned hx, lx, hy, ly;
    pksplit(W[ka * HID_ + n], W[(ka + 1) * HID_ + n], hx, lx);
    pksplit(W[(ka + 8) * HID_ + n], W[(ka + 9) * HID_ + n], hy, ly);
    uint2 vh; vh.x = hx; vh.y = hy;
    uint2 vl; vl.x = lx; vl.y = ly;
    g_w1s[0][f][n] = vh;
    g_w1s[1][f][n] = vl;
}

__global__ void prep_w2_kernel(const float* __restrict__ W) {
    int t = blockIdx.x * 256 + threadIdx.x;
    if (t >= 4 * 8 * 128) return;
    int ch = t >> 10, f = (t >> 7) & 7, n = t & 127;
    int ks = f >> 2, klo = f & 3;
    int ka = ch * 32 + 2 * (ks * 8 + klo);
    unsigned hx, lx, hy, ly;
    pksplit(W[ka * HID_ + n], W[(ka + 1) * HID_ + n], hx, lx);
    pksplit(W[(ka + 8) * HID_ + n], W[(ka + 9) * HID_ + n], hy, ly);
    uint2 vh; vh.x = hx; vh.y = hy;
    uint2 vl; vl.x = lx; vl.y = ly;
    g_w2s[0][ch][f][n] = vh;
    g_w2s[1][ch][f][n] = vl;
}

// ---------------------------------------------------------------------------
// conv1 + relu + maxpool2 : x[B,9,2048] -> g_o1[B,16,1024]   (R8 form)
// grid (1024, 8), 128 threads
// ---------------------------------------------------------------------------
__global__ void conv1_kernel(const float* __restrict__ x,
                             const float* __restrict__ w,
                             const float* __restrict__ bias) {
    __shared__ float xs[9][260];
    __shared__ unsigned long long ws2[720];   // duplicated weights {w,w}
    __shared__ float bs[16];
    const int b = blockIdx.x, t0 = blockIdx.y * 128, tid = threadIdx.x;

    for (int e = tid; e < 720; e += 128) ws2[e] = dup2(w[e]);
    if (tid < 16) bs[tid] = bias[tid];

    const float* xb = x + (size_t)b * 9 * T_;
    const int base = 2 * t0 - 2;
    for (int e = tid; e < 9 * 260; e += 128) {
        int ci = e / 260, j = e % 260;
        int t = base + j;
        xs[ci][j] = (t >= 0 && t < T_) ? xb[ci * T_ + t] : 0.f;
    }
    __syncthreads();

    const int lt = tid;
    unsigned long long xp[9][5];
#pragma unroll
    for (int ci = 0; ci < 9; ci++) {
        float xv[6];
#pragma unroll
        for (int j = 0; j < 6; j++) xv[j] = xs[ci][2 * lt + j];
#pragma unroll
        for (int k = 0; k < 5; k++) xp[ci][k] = packf2(xv[k], xv[k + 1]);
    }

    float* ob = g_o1 + (size_t)b * 16 * T1_ + (t0 + lt);
#pragma unroll
    for (int co = 0; co < 16; co++) {
        unsigned long long a = 0ull;
#pragma unroll
        for (int ci = 0; ci < 9; ci++)
#pragma unroll
            for (int k = 0; k < 5; k++)
                FFMA2(a, ws2[(co * 9 + ci) * 5 + k], xp[ci][k]);
        float lo = __uint_as_float((unsigned)(a & 0xffffffffull));
        float hi = __uint_as_float((unsigned)(a >> 32));
        ob[(size_t)co * T1_] = fmaxf(fmaxf(lo, hi) + bs[co], 0.f);
    }
}

// ---------------------------------------------------------------------------
// conv2 + relu + maxpool2 : g_o1[B,16,1024] -> g_o2[B,32,512]   (R8 form)
// grid (1024, 4), 128 threads
// ---------------------------------------------------------------------------
__global__ void conv2_kernel(const float* __restrict__ w,
                             const float* __restrict__ bias) {
    __shared__ float xs[16][260];
    __shared__ unsigned long long ws2[2560];
    __shared__ float bs[32];
    const int b = blockIdx.x, t0 = blockIdx.y * 128, tid = threadIdx.x;

    for (int e = tid; e < 2560; e += 128) ws2[e] = dup2(w[e]);
    if (tid < 32) bs[tid] = bias[tid];

    const float* xb = g_o1 + (size_t)b * 16 * T1_;
    const int base = 2 * t0 - 2;
    for (int e = tid; e < 16 * 260; e += 128) {
        int ci = e / 260, j = e % 260;
        int t = base + j;
        xs[ci][j] = (t >= 0 && t < T1_) ? xb[ci * T1_ + t] : 0.f;
    }
    __syncthreads();

    const int lt = tid;
    unsigned long long a[32];
#pragma unroll
    for (int co = 0; co < 32; co++) a[co] = 0ull;

#pragma unroll 2
    for (int ci = 0; ci < 16; ci++) {
        float xv[6];
#pragma unroll
        for (int j = 0; j < 6; j++) xv[j] = xs[ci][2 * lt + j];
        unsigned long long xp[5];
#pragma unroll
        for (int k = 0; k < 5; k++) xp[k] = packf2(xv[k], xv[k + 1]);
#pragma unroll
        for (int co = 0; co < 32; co++)
#pragma unroll
            for (int k = 0; k < 5; k++)
                FFMA2(a[co], ws2[(co * 16 + ci) * 5 + k], xp[k]);
    }

    float* ob = g_o2 + (size_t)b * 32 * RT_ + (t0 + lt);
#pragma unroll
    for (int co = 0; co < 32; co++) {
        float lo = __uint_as_float((unsigned)(a[co] & 0xffffffffull));
        float hi = __uint_as_float((unsigned)(a[co] >> 32));
        ob[(size_t)co * RT_] = fmaxf(fmaxf(lo, hi) + bs[co], 0.f);
    }
}

// ---------------------------------------------------------------------------
// GCN1 (bf16 mma, pre-split W): z = Anorm*o2 (stencil), h1 = relu(z@W1+b1)
// 128 rows x 128 cols, K=32 (2 ksteps). 8 warps = 4m x 2n. grid 4096.
// ---------------------------------------------------------------------------
__global__ __launch_bounds__(256) void gcn1_kernel(const float* __restrict__ bias) {
    __shared__ uint2 za[16][68];
    __shared__ uint2 wph[8][132];
    __shared__ uint2 wpl[8][132];
    __shared__ float bsm[128];
    const int bx = blockIdx.x, b = bx >> 2, p0 = (bx & 3) << 7;
    const int tid = threadIdx.x, lane = tid & 31, warp = tid >> 5;
    const int wm = warp >> 1, wn = warp & 1, l4 = lane & 3, l8 = lane >> 2;

    if (tid < 128) bsm[tid] = bias[tid];

    // fill wph/wpl from pre-split weights (coalesced uint2 copies)
    for (int e = tid; e < 1024; e += 256) {
        int f = e >> 7, n = e & 127;
        wph[f][n] = g_w1s[0][f][n];
        wpl[f][n] = g_w1s[1][f][n];
    }
    // fill za: stencil over g_o2 [b][32 f][512 p]
    {
        const float* gb = g_o2 + (size_t)b * 32 * RT_;
        const int kp = 2 * warp + (lane >> 4);
        const int rl = lane & 15;
#pragma unroll
        for (int i = 0; i < 4; i++) {
            int ridx = rl + 16 * i;
            int r0 = ((ridx >> 3) << 4) + (ridx & 7);
            uint2 v;
#pragma unroll
            for (int h = 0; h < 2; h++) {
                int pp = p0 + r0 + h * 8;
                float di = (pp == 0 || pp == RT_ - 1) ? RS2 : RS3;
                const float* c0 = gb + (2 * kp) * RT_ + pp;
                const float* c1 = gb + (2 * kp + 1) * RT_ + pp;
                float z0 = di * di * c0[0];
                float z1 = di * di * c1[0];
                if (pp > 0) {
                    float dp = (pp == 1) ? RS2 : RS3;
                    z0 += di * dp * c0[-1];
                    z1 += di * dp * c1[-1];
                }
                if (pp < RT_ - 1) {
                    float dn = (pp == RT_ - 2) ? RS2 : RS3;
                    z0 += di * dn * c0[1];
                    z1 += di * dn * c1[1];
                }
                unsigned wv = pk(z0, z1);
                if (h == 0) v.x = wv; else v.y = wv;
            }
            za[kp][ridx] = v;
        }
    }
    __syncthreads();

    float acc[2][8][4] = {};
#pragma unroll
    for (int ks = 0; ks < 2; ks++) {
        unsigned a[2][4];
#pragma unroll
        for (int i = 0; i < 2; i++) {
            int mt = wm * 2 + i;
            uint2 lo = za[ks * 8 + l4][mt * 8 + l8];
            uint2 hi = za[ks * 8 + 4 + l4][mt * 8 + l8];
            a[i][0] = lo.x; a[i][1] = lo.y; a[i][2] = hi.x; a[i][3] = hi.y;
        }
#pragma unroll
        for (int j = 0; j < 8; j++) {
            uint2 bh = wph[ks * 4 + l4][wn * 64 + j * 8 + l8];
            uint2 bl = wpl[ks * 4 + l4][wn * 64 + j * 8 + l8];
#pragma unroll
            for (int i = 0; i < 2; i++) {
                mma_bf16(acc[i][j], a[i][0], a[i][1], a[i][2], a[i][3], bh.x, bh.y);
                mma_bf16(acc[i][j], a[i][0], a[i][1], a[i][2], a[i][3], bl.x, bl.y);
            }
        }
    }

    // epilogue: relu(acc + bias) -> g_h1 bf16x2 words
    unsigned* h1w = (unsigned*)g_h1;
#pragma unroll
    for (int i = 0; i < 2; i++) {
#pragma unroll
        for (int j = 0; j < 8; j++) {
            int cb = wn * 64 + j * 8 + 2 * l4;
            float b0 = bsm[cb], b1 = bsm[cb + 1];
            int R0 = wm * 32 + i * 16 + l8;
            size_t node = (size_t)b * RT_ + p0 + R0;
            int cw = cb >> 1;
            h1w[node * 64 + cw] =
                pk(fmaxf(acc[i][j][0] + b0, 0.f), fmaxf(acc[i][j][1] + b1, 0.f));
            h1w[(node + 8) * 64 + cw] =
                pk(fmaxf(acc[i][j][2] + b0, 0.f), fmaxf(acc[i][j][3] + b1, 0.f));
        }
    }
}

// ---------------------------------------------------------------------------
// GCN2 (bf16 mma, pre-split W): z2 = Anorm*h1 (stencil), acc = z2@W2,
// epilogue relu + bias + per-batch column sums -> g_bsum.
// 128 rows x 128 cols, K=128 in 4 chunks of 32 (2 ksteps each). grid 4096.
// ---------------------------------------------------------------------------
__global__ __launch_bounds__(256) void gcn2_kernel(const float* __restrict__ bias) {
    __shared__ uint2 za[16][68];
    __shared__ uint2 wph[8][132];
    __shared__ uint2 wpl[8][132];
    __shared__ float red[4][128];
    __shared__ float bsm[128];
    const int bx = blockIdx.x, b = bx >> 2, p0 = (bx & 3) << 7;
    const int tid = threadIdx.x, lane = tid & 31, warp = tid >> 5;
    const int wm = warp >> 1, wn = warp & 1, l4 = lane & 3, l8 = lane >> 2;

    if (tid < 128) bsm[tid] = bias[tid];

    float acc[2][8][4] = {};

    const unsigned* h1w = (const unsigned*)g_h1;
    const int fkp = tid & 15;          // k-pair 0..15 within chunk
    const int rb  = tid >> 4;          // ridx base 0..15

    for (int ch = 0; ch < 4; ch++) {
        const int k0 = ch * 32;
        if (ch) __syncthreads();
        // fill wph/wpl from pre-split weights
        for (int e = tid; e < 1024; e += 256) {
            int f = e >> 7, n = e & 127;
            wph[f][n] = g_w2s[0][ch][f][n];
            wpl[f][n] = g_w2s[1][ch][f][n];
        }
        // fill za: stencil over bf16 h1 words
        {
            const int cw = (k0 >> 1) + fkp;
#pragma unroll
            for (int i = 0; i < 4; i++) {
                int ridx = rb + 16 * i;
                int r0 = ((ridx >> 3) << 4) + (ridx & 7);
                uint2 v;
#pragma unroll
                for (int h = 0; h < 2; h++) {
                    int pp = p0 + r0 + h * 8;
                    size_t node = (size_t)b * RT_ + pp;
                    float di = (pp == 0 || pp == RT_ - 1) ? RS2 : RS3;
                    float2 c = upk(h1w[node * 64 + cw]);
                    float zx = di * di * c.x, zy = di * di * c.y;
                    if (pp > 0) {
                        float dp = (pp == 1) ? RS2 : RS3;
                        float2 t = upk(h1w[(node - 1) * 64 + cw]);
                        zx += di * dp * t.x; zy += di * dp * t.y;
                    }
                    if (pp < RT_ - 1) {
                        float dn = (pp == RT_ - 2) ? RS2 : RS3;
                        float2 t = upk(h1w[(node + 1) * 64 + cw]);
                        zx += di * dn * t.x; zy += di * dn * t.y;
                    }
                    unsigned wv = pk(zx, zy);
                    if (h == 0) v.x = wv; else v.y = wv;
                }
                za[fkp][ridx] = v;
            }
        }
        __syncthreads();

#pragma unroll
        for (int ks = 0; ks < 2; ks++) {
            unsigned a[2][4];
#pragma unroll
            for (int i = 0; i < 2; i++) {
                int mt = wm * 2 + i;
                uint2 lo = za[ks * 8 + l4][mt * 8 + l8];
                uint2 hi = za[ks * 8 + 4 + l4][mt * 8 + l8];
                a[i][0] = lo.x; a[i][1] = lo.y; a[i][2] = hi.x; a[i][3] = hi.y;
            }
#pragma unroll
            for (int j = 0; j < 8; j++) {
                uint2 bh = wph[ks * 4 + l4][wn * 64 + j * 8 + l8];
                uint2 bl = wpl[ks * 4 + l4][wn * 64 + j * 8 + l8];
#pragma unroll
                for (int i = 0; i < 2; i++) {
                    mma_bf16(acc[i][j], a[i][0], a[i][1], a[i][2], a[i][3], bh.x, bh.y);
                    mma_bf16(acc[i][j], a[i][0], a[i][1], a[i][2], a[i][3], bl.x, bl.y);
                }
            }
        }
    }

    // --- epilogue: relu(acc + bias), column sums, warp bfly reduce ---
    float s[8][2];
#pragma unroll
    for (int j = 0; j < 8; j++) {
        int colb = wn * 64 + j * 8 + 2 * l4;
        float b0v = bsm[colb], b1v = bsm[colb + 1];
        float s0 = 0.f, s1 = 0.f;
#pragma unroll
        for (int i = 0; i < 2; i++) {
            s0 += fmaxf(acc[i][j][0] + b0v, 0.f) + fmaxf(acc[i][j][2] + b0v, 0.f);
            s1 += fmaxf(acc[i][j][1] + b1v, 0.f) + fmaxf(acc[i][j][3] + b1v, 0.f);
        }
        s[j][0] = s0;
        s[j][1] = s1;
    }
#pragma unroll
    for (int j = 0; j < 8; j++)
#pragma unroll
        for (int lo = 0; lo < 2; lo++) {
            float v = s[j][lo];
            v += __shfl_xor_sync(0xffffffffu, v, 4);
            v += __shfl_xor_sync(0xffffffffu, v, 8);
            v += __shfl_xor_sync(0xffffffffu, v, 16);
            s[j][lo] = v;
        }
    if (lane < 4) {
#pragma unroll
        for (int j = 0; j < 8; j++)
#pragma unroll
            for (int lo = 0; lo < 2; lo++)
                red[wm][wn * 64 + j * 8 + 2 * lane + lo] = s[j][lo];
    }
    __syncthreads();

    if (tid < 128) {
        float t = red[0][tid] + red[1][tid] + red[2][tid] + red[3][tid];
        g_bsum[((size_t)b * 4 + (bx & 3)) * HID_ + tid] = t;
    }
}

// ---------------------------------------------------------------------------
// mean over RT (sum of 4 chunk partials / 512) then fc
// ---------------------------------------------------------------------------
__global__ void fc_kernel(const float* __restrict__ fw,
                          const float* __restrict__ fb,
                          float* __restrict__ out) {
    __shared__ float s[128];
    const int b = blockIdx.x, o = threadIdx.x;
    {
        float v0 = 0.f, v1 = 0.f;
#pragma unroll
        for (int c = 0; c < 4; c++) {
            v0 += g_bsum[((size_t)b * 4 + c) * HID_ + o];
            v1 += g_bsum[((size_t)b * 4 + c) * HID_ + o + 64];
        }
        s[o] = v0;
        s[o + 64] = v1;
    }
    __syncthreads();
    float a = 0.f;
#pragma unroll
    for (int k = 0; k < 128; k++) a += s[k] * fw[k * 64 + o];
    out[b * 64 + o] = a * (1.f / 512.f) + fb[o];
}

// ---------------------------------------------------------------------------
extern "C" void kernel_launch(void* const* d_in, const int* in_sizes, int n_in,
                              void* d_out, int out_size) {
    const float* x   = (const float*)d_in[0];
    const float* c1w = (const float*)d_in[1];
    const float* c1b = (const float*)d_in[2];
    const float* c2w = (const float*)d_in[3];
    const float* c2b = (const float*)d_in[4];
    const float* g1w = (const float*)d_in[5];
    const float* g1b = (const float*)d_in[6];
    const float* g2w = (const float*)d_in[7];
    const float* g2b = (const float*)d_in[8];
    const float* fw  = (const float*)d_in[9];
    const float* fb  = (const float*)d_in[10];
    float* out = (float*)d_out;

    prep_w1_kernel<<<4, 256>>>(g1w);
    prep_w2_kernel<<<16, 256>>>(g2w);
    conv1_kernel<<<dim3(B_, 8), 128>>>(x, c1w, c1b);
    conv2_kernel<<<dim3(B_, 4), 128>>>(c2w, c2b);
    gcn1_kernel<<<B_ * 4, 256>>>(g1b);
    gcn2_kernel<<<B_ * 4, 256>>>(g2b);
    fc_kernel<<<B_, 64>>>(fw, fb, out);
}